// round 10
// baseline (speedup 1.0000x reference)
#include <cuda_runtime.h>
#include <math.h>

// Problem constants
#define BATCH 128
#define TLEN 160000

// Decomposition: small blocks -> 32 blocks/SM -> deep cross-block phase overlap
#define CHUNK 25                  // samples per thread (odd -> conflict-free smem stride)
#define NTHREADS 64               // threads per block
#define REGION (CHUNK * NTHREADS) // 1600 samples per block
#define WARM 16                   // warmup steps: per-parity decay 0.1716^8 ~ 7.5e-7
#define SMEM_FLOATS (REGION + WARM)   // 1616 floats = 6464 bytes -> 32 blocks/SM
#define BLOCKS_PER_CH (TLEN / REGION) // 100
#define NBLOCKS (BATCH * BLOCKS_PER_CH) // 12800

// Biquad with cutoff = fs/4: cos(w0)=0 => a1=0 exactly.
// y[n] = b0*(x[n] + x[n-2]) + b1*x[n-1] - a2*y[n-2]
// Even/odd chains decouple -> 1 dependent FFMA per 2 samples.

__global__ void __launch_bounds__(NTHREADS)
biquad_kernel(const float* __restrict__ x, float* __restrict__ y,
              float b0, float b1, float a2)
{
    extern __shared__ float s[];  // [WARM halo | REGION samples]
    const int tid = threadIdx.x;
    const int blk = blockIdx.x;
    const int ch  = blk / BLOCKS_PER_CH;
    const int s0  = (blk % BLOCKS_PER_CH) * REGION;
    const long base = (long)ch * TLEN + s0;

    // ---- Stage input: coalesced float4 streaming loads (touched once -> evict-first) ----
    {
        const float4* __restrict__ xin = (const float4*)(x + base);
        float4* s4 = (float4*)(s + WARM);   // WARM=16 floats = 64B, 16B-aligned
        #pragma unroll
        for (int i = tid; i < REGION / 4; i += NTHREADS)   // 400 elems, 7 ragged iters
            s4[i] = __ldcs(&xin[i]);
        // 16-sample halo before the region (zeros at channel start == exact zero ICs)
        if (tid < WARM)
            s[tid] = (s0 == 0) ? 0.0f : __ldcs(&x[base - WARM + tid]);
    }
    __syncthreads();

    // ---- Warmup: 16 steps from zero state (smem stride 25 -> conflict-free) ----
    const int p = WARM + tid * CHUNK;
    float x1 = 0.0f, x2 = 0.0f, y1 = 0.0f, y2 = 0.0f;
    #pragma unroll
    for (int t = 0; t < WARM; ++t) {
        float xv = s[p - WARM + t];
        float fir = fmaf(b0, xv + x2, b1 * x1);   // off critical path
        float yv  = fmaf(-a2, y2, fir);           // chain: y[n] <- y[n-2]
        x2 = x1; x1 = xv;
        y2 = y1; y1 = yv;
    }
    __syncthreads();  // warmup reads (into neighbors' chunks) done before in-place writes

    // ---- Main: filter chunk in place in SMEM (unroll x2: parities pipeline) ----
    #pragma unroll
    for (int t = 0; t < CHUNK - 1; t += 2) {
        float xa = s[p + t];
        float xb = s[p + t + 1];
        float fa = fmaf(b0, xa + x2, b1 * x1);
        float ya = fmaf(-a2, y2, fa);             // even chain
        float fb = fmaf(b0, xb + x1, b1 * xa);
        float yb = fmaf(-a2, y1, fb);             // odd chain (independent)
        s[p + t]     = ya;
        s[p + t + 1] = yb;
        x2 = xa; x1 = xb;
        y2 = ya; y1 = yb;
    }
    {   // tail sample (CHUNK odd)
        float xv = s[p + CHUNK - 1];
        float fir = fmaf(b0, xv + x2, b1 * x1);
        float yv  = fmaf(-a2, y2, fir);
        s[p + CHUNK - 1] = yv;
    }
    __syncthreads();

    // ---- Store output: coalesced float4 streaming stores ----
    {
        const float4* s4 = (const float4*)(s + WARM);
        float4* __restrict__ yout = (float4*)(y + base);
        #pragma unroll
        for (int i = tid; i < REGION / 4; i += NTHREADS)
            __stcs(&yout[i], s4[i]);
    }
}

extern "C" void kernel_launch(void* const* d_in, const int* in_sizes, int n_in,
                              void* d_out, int out_size)
{
    const float* x = (const float*)d_in[0];
    float* y = (float*)d_out;

    // torchaudio lowpass_biquad coefficients (double math, then float32)
    const double PI = 3.14159265358979323846;
    double w0    = 2.0 * PI * 8000.0 / 32000.0;
    double alpha = sin(w0) / (2.0 * 0.707);
    double cw    = cos(w0);           // ~6e-17: a1 term dropped (|a1*y|~1e-16)
    double b0d = (1.0 - cw) / 2.0;
    double b1d = 1.0 - cw;
    double a0d = 1.0 + alpha;
    double a2d = 1.0 - alpha;
    float b0 = (float)(b0d / a0d);
    float b1 = (float)(b1d / a0d);
    float a2 = (float)(a2d / a0d);

    biquad_kernel<<<NBLOCKS, NTHREADS, SMEM_FLOATS * sizeof(float)>>>(
        x, y, b0, b1, a2);
}

// round 11
// speedup vs baseline: 1.1250x; 1.1250x over previous
#include <cuda_runtime.h>
#include <math.h>

// Problem constants
#define BATCH 128
#define TLEN  160000

// Decomposition: warp-parallel scan, no smem, no barriers
#define TILE        128                 // samples per warp-tile (float4 per lane)
#define TILES_PER_W 10                  // tiles per warp segment
#define SEG         (TILE * TILES_PER_W)    // 1280 samples
#define WARPS_PER_CH (TLEN / SEG)       // 125
#define NWARPS      (BATCH * WARPS_PER_CH)  // 16000
#define NTHREADS    256                 // 8 warps/block
#define NBLOCKS     (NWARPS * 32 / NTHREADS) // 2000

// Biquad @ cutoff=fs/4: cos(w0)=0 => a1=0, b2=b0.
//   y[n] = f[n] - a2*y[n-2],  f[n] = b0*(x[n]+x[n-2]) + b1*x[n-1]
// Per-parity chain: first-order recurrence with CONSTANT coeff c2=a2^2
//   E_l = c2*E_{l-1} + dE_l  -> Kogge-Stone scan (coeff squares each step).

__device__ __forceinline__ void tile_step(
    float4 xv, int lane,
    float b0, float b1, float a2, float c2, float pwE,
    float& xm1, float& xm2, float& yin_e, float& yin_o,
    float4& yout)
{
    const unsigned FULL = 0xFFFFFFFFu;
    // neighbor x from lane-1 (x[4l-2], x[4l-1]); lane 0 uses carries
    float pz = __shfl_up_sync(FULL, xv.z, 1);
    float pw_ = __shfl_up_sync(FULL, xv.w, 1);
    float xa2 = (lane == 0) ? xm2 : pz;
    float xa1 = (lane == 0) ? xm1 : pw_;
    // FIR part f[n]
    float f0 = fmaf(b0, xv.x + xa2, b1 * xa1);
    float f1 = fmaf(b0, xv.y + xa1, b1 * xv.x);
    float f2 = fmaf(b0, xv.z + xv.x, b1 * xv.y);
    float f3 = fmaf(b0, xv.w + xv.y, b1 * xv.z);
    // per-lane combined increments for the two-parity chains
    float dE = fmaf(-a2, f0, f2);   // y[4l+2] = dE + c2*y[4l-2]
    float dO = fmaf(-a2, f1, f3);   // y[4l+3] = dO + c2*y[4l-1]
    // Kogge-Stone scan, constant coefficient (squares each step)
    float m = c2;
    #pragma unroll
    for (int s = 1; s < 32; s <<= 1) {
        float tE = __shfl_up_sync(FULL, dE, s);
        float tO = __shfl_up_sync(FULL, dO, s);
        if (lane >= s) { dE = fmaf(m, tE, dE); dO = fmaf(m, tO, dO); }
        m = m * m;
    }
    // add incoming-state contribution: c2^(lane+1) * y_in
    float yE2 = fmaf(pwE, yin_e, dE);   // y[4l+2]
    float yO3 = fmaf(pwE, yin_o, dO);   // y[4l+3]
    // first sample of each parity from neighbor's scanned value
    float pE = __shfl_up_sync(FULL, yE2, 1);
    float pO = __shfl_up_sync(FULL, yO3, 1);
    float yprevE = (lane == 0) ? yin_e : pE;   // y[4l-2]
    float yprevO = (lane == 0) ? yin_o : pO;   // y[4l-1]
    float yE0 = fmaf(-a2, yprevE, f0);  // y[4l]
    float yO1 = fmaf(-a2, yprevO, f1);  // y[4l+1]
    yout = make_float4(yE0, yO1, yE2, yO3);
    // carry state out of tile (lane 31 holds samples 124..127)
    yin_e = __shfl_sync(FULL, yE2, 31);   // y[126]
    yin_o = __shfl_sync(FULL, yO3, 31);   // y[127]
    xm2   = __shfl_sync(FULL, xv.z, 31);  // x[126]
    xm1   = __shfl_sync(FULL, xv.w, 31);  // x[127]
}

__global__ void __launch_bounds__(NTHREADS)
biquad_kernel(const float* __restrict__ x, float* __restrict__ y,
              float b0, float b1, float a2)
{
    const int gtid = blockIdx.x * NTHREADS + threadIdx.x;
    const int w    = gtid >> 5;
    const int lane = gtid & 31;
    const int ch   = w / WARPS_PER_CH;
    const int seg  = w % WARPS_PER_CH;
    const long base = (long)ch * TLEN + (long)seg * SEG;

    const float4* __restrict__ xin  = (const float4*)(x + base);
    float4* __restrict__       yo4  = (float4*)(y + base);

    const float c2 = a2 * a2;
    // pwE = c2^(lane+1) by repeated squaring
    float pwE = c2, bse = c2;
    int e = lane;
    #pragma unroll
    for (int i = 0; i < 5; ++i) { if (e & 1) pwE *= bse; bse *= bse; e >>= 1; }

    float xm1 = 0.0f, xm2 = 0.0f, yin_e = 0.0f, yin_o = 0.0f;

    // Warmup tile (128 samples before segment) for mid-channel segments.
    // Zero-IC start error decays by c2^64 ~ 1e-98 -> exact in fp32.
    // Channel-start segments keep true zero ICs (exact).
    if (seg > 0) {
        float4 xw = __ldcs(&xin[-32 + lane]);
        float4 dump;
        tile_step(xw, lane, b0, b1, a2, c2, pwE, xm1, xm2, yin_e, yin_o, dump);
    }

    // Main tiles with next-tile prefetch
    float4 xc = __ldcs(&xin[lane]);
    #pragma unroll
    for (int t = 0; t < TILES_PER_W; ++t) {
        float4 xn;
        if (t < TILES_PER_W - 1) xn = __ldcs(&xin[(t + 1) * 32 + lane]);
        float4 yo;
        tile_step(xc, lane, b0, b1, a2, c2, pwE, xm1, xm2, yin_e, yin_o, yo);
        __stcs(&yo4[t * 32 + lane], yo);
        xc = xn;
    }
}

extern "C" void kernel_launch(void* const* d_in, const int* in_sizes, int n_in,
                              void* d_out, int out_size)
{
    const float* x = (const float*)d_in[0];
    float* y = (float*)d_out;

    // torchaudio lowpass_biquad coefficients (double math, then float32)
    const double PI = 3.14159265358979323846;
    double w0    = 2.0 * PI * 8000.0 / 32000.0;
    double alpha = sin(w0) / (2.0 * 0.707);
    double cw    = cos(w0);           // ~6e-17: a1 term exactly negligible
    double b0d = (1.0 - cw) / 2.0;
    double b1d = 1.0 - cw;
    double a0d = 1.0 + alpha;
    double a2d = 1.0 - alpha;
    float b0 = (float)(b0d / a0d);
    float b1 = (float)(b1d / a0d);
    float a2 = (float)(a2d / a0d);

    biquad_kernel<<<NBLOCKS, NTHREADS>>>(x, y, b0, b1, a2);
}

// round 12
// speedup vs baseline: 1.2000x; 1.0667x over previous
#include <cuda_runtime.h>
#include <math.h>

// Problem constants
#define BATCH 128
#define TLEN  160000

// Decomposition: warp-parallel scan, no smem, no barriers
#define TILE        128                 // samples per warp-tile (float4 per lane)
#define TILES_PER_W 10                  // tiles per warp segment
#define SEG         (TILE * TILES_PER_W)    // 1280 samples
#define WARPS_PER_CH (TLEN / SEG)       // 125
#define NWARPS      (BATCH * WARPS_PER_CH)  // 16000
#define NTHREADS    256                 // 8 warps/block
#define NBLOCKS     (NWARPS * 32 / NTHREADS) // 2000

// Biquad @ cutoff=fs/4: cos(w0)=0 => a1=0, b2=b0.
//   y[n] = f[n] - a2*y[n-2],  f[n] = b0*(x[n]+x[n-2]) + b1*x[n-1]
// Per-parity first-order chains with constant coeff c2=a2^2 = 0.0295.
// 3-step Kogge-Stone suffices: omitted terms weighted c2^8 = 5.7e-13 (sub-fp32).
// Carries ride the rotate shuffle: lane0 receives lane31's value = next carry.

__device__ __forceinline__ void tile_step(
    float4 xv, int lane,
    float b0, float b1, float a2, float c2,
    float& xm1, float& xm2, float& yin_e, float& yin_o,
    float4& yout)
{
    const unsigned FULL = 0xFFFFFFFFu;
    const int rot = (lane + 31) & 31;

    // neighbor x via rotate: lanes>=1 get lane-1's value; lane0 slot = lane31's (next carry)
    float rz = __shfl_sync(FULL, xv.z, rot);
    float rw = __shfl_sync(FULL, xv.w, rot);
    float xa2 = (lane == 0) ? xm2 : rz;   // x[4l-2]
    float xa1 = (lane == 0) ? xm1 : rw;   // x[4l-1]
    xm2 = rz; xm1 = rw;                   // only lane0's copy matters next tile

    // FIR part f[n]
    float f0 = fmaf(b0, xv.x + xa2, b1 * xa1);
    float f1 = fmaf(b0, xv.y + xa1, b1 * xv.x);
    float f2 = fmaf(b0, xv.z + xv.x, b1 * xv.y);
    float f3 = fmaf(b0, xv.w + xv.y, b1 * xv.z);

    // per-lane combined increments for the two parity chains
    float dE = fmaf(-a2, f0, f2);   // y[4l+2] = dE + c2*y[4l-2]
    float dO = fmaf(-a2, f1, f3);
    // seed incoming state into lane 0: scan propagates it with weights c2^(l+1)
    if (lane == 0) { dE = fmaf(c2, yin_e, dE); dO = fmaf(c2, yin_o, dO); }

    // 3-step Kogge-Stone, constant coefficient (squares each step)
    float m = c2;
    #pragma unroll
    for (int s = 1; s <= 4; s <<= 1) {
        float tE = __shfl_up_sync(FULL, dE, s);
        float tO = __shfl_up_sync(FULL, dO, s);
        if (lane >= s) { dE = fmaf(m, tE, dE); dO = fmaf(m, tO, dO); }
        m = m * m;
    }
    float yE2 = dE;   // y[4l+2]
    float yO3 = dO;   // y[4l+3]

    // previous y via rotate; lane0 uses carry; lane0's rotate value = next carry
    float rE = __shfl_sync(FULL, yE2, rot);
    float rO = __shfl_sync(FULL, yO3, rot);
    float yprevE = (lane == 0) ? yin_e : rE;   // y[4l-2]
    float yprevO = (lane == 0) ? yin_o : rO;   // y[4l-1]
    yin_e = rE; yin_o = rO;

    float yE0 = fmaf(-a2, yprevE, f0);  // y[4l]
    float yO1 = fmaf(-a2, yprevO, f1);  // y[4l+1]
    yout = make_float4(yE0, yO1, yE2, yO3);
}

__global__ void __launch_bounds__(NTHREADS)
biquad_kernel(const float* __restrict__ x, float* __restrict__ y,
              float b0, float b1, float a2)
{
    const int gtid = blockIdx.x * NTHREADS + threadIdx.x;
    const int w    = gtid >> 5;
    const int lane = gtid & 31;
    const int ch   = w / WARPS_PER_CH;
    const int seg  = w % WARPS_PER_CH;
    const long base = (long)ch * TLEN + (long)seg * SEG;

    const float4* __restrict__ xin = (const float4*)(x + base);
    float4* __restrict__       yo4 = (float4*)(y + base);

    const float c2 = a2 * a2;
    float xm1 = 0.0f, xm2 = 0.0f, yin_e = 0.0f, yin_o = 0.0f;

    // Warmup tile for mid-channel segments (state decay c2^64 ~ 1e-98 -> exact).
    // Channel-start segments keep true zero ICs (exact).
    if (seg > 0) {
        float4 xw = __ldcs(&xin[-32 + lane]);
        float4 dump;
        tile_step(xw, lane, b0, b1, a2, c2, xm1, xm2, yin_e, yin_o, dump);
    }

    // Main tiles, prefetch depth 2
    float4 xa = __ldcs(&xin[lane]);
    float4 xb = __ldcs(&xin[32 + lane]);
    #pragma unroll
    for (int t = 0; t < TILES_PER_W; ++t) {
        float4 xn;
        if (t + 2 < TILES_PER_W) xn = __ldcs(&xin[(t + 2) * 32 + lane]);
        float4 yo;
        tile_step(xa, lane, b0, b1, a2, c2, xm1, xm2, yin_e, yin_o, yo);
        __stcs(&yo4[t * 32 + lane], yo);
        xa = xb; xb = xn;
    }
}

extern "C" void kernel_launch(void* const* d_in, const int* in_sizes, int n_in,
                              void* d_out, int out_size)
{
    const float* x = (const float*)d_in[0];
    float* y = (float*)d_out;

    // torchaudio lowpass_biquad coefficients (double math, then float32)
    const double PI = 3.14159265358979323846;
    double w0    = 2.0 * PI * 8000.0 / 32000.0;
    double alpha = sin(w0) / (2.0 * 0.707);
    double cw    = cos(w0);           // ~6e-17: a1 term exactly negligible
    double b0d = (1.0 - cw) / 2.0;
    double b1d = 1.0 - cw;
    double a0d = 1.0 + alpha;
    double a2d = 1.0 - alpha;
    float b0 = (float)(b0d / a0d);
    float b1 = (float)(b1d / a0d);
    float a2 = (float)(a2d / a0d);

    biquad_kernel<<<NBLOCKS, NTHREADS>>>(x, y, b0, b1, a2);
}